// round 14
// baseline (speedup 1.0000x reference)
#include <cuda_runtime.h>
#include <mma.h>

using namespace nvcuda;

#define N_NODES 100000
#define N_EDGES 1600000
#define D_F     128
#define D_CAT   256
#define D_U1    214
#define D_U2    172
#define D_OUT   128

#define E_TILE   128
#define N_TILES  (N_EDGES / E_TILE)   // 12500
#define EGRID    148
#define HP 136                        // h pitch (floats)
#define ETHREADS 512

// ---- k_edge dynamic smem byte offsets ----
#define SB_H1   0                     // h1 [128][HP] : 69632 B
#define SB_H2   69632                 // h2 [128][HP] : 69632 B
#define SB_W3   139264                // W3 tf32 resident [128][128] : 65536 B
#define SB_BM2  204800                // bias2 mat [128][16] : 8192 B
#define SB_BM3  212992                // bias3 mat [128][16] : 8192 B
#define SB_W1   221184                // 640 floats : 2560 B
#define SB_B1   223744                // 512 B
#define SB_EA   224256                // 2 x 640 floats : 5120 B
#define SB_DST  229376                // 2 x 128 ints : 1024 B
#define EDGE_SMEM_BYTES 230400

// ---------------- scratch ----------------
__device__ float g_aggr[N_NODES * D_F];
__device__ float g_nrm [N_NODES * D_CAT];
__device__ float g_u1  [N_NODES * D_U1];
__device__ float g_u2  [N_NODES * D_U2];
__device__ float g_w1t [D_U1 * D_CAT];
__device__ float g_w2t [D_U2 * D_U1];
__device__ float g_w3t [D_OUT * D_U2];

// ---------------- helpers ----------------
__device__ __forceinline__ float leaky(float v) { return v > 0.f ? v : 0.01f * v; }

__device__ __forceinline__ float tf32f(float x) {
    unsigned r; asm("cvt.rna.tf32.f32 %0, %1;" : "=r"(r) : "f"(x));
    return __uint_as_float(r);
}
__device__ __forceinline__ void red_f32(float* p, float v) {
    asm volatile("red.global.add.f32 [%0], %1;" :: "l"(p), "f"(v) : "memory");
}
__device__ __forceinline__ void cp_async4(unsigned saddr, const void* g) {
    asm volatile("cp.async.ca.shared.global [%0], [%1], 4;" :: "r"(saddr), "l"(g));
}
#define CP_COMMIT() asm volatile("cp.async.commit_group;" ::: "memory")
#define CP_WAIT(n)  asm volatile("cp.async.wait_group %0;" :: "n"(n) : "memory")

// ---------------- kernel: nop (ncu capture alignment) ----------------
__global__ void k_nop() {}

// ---------------- kernel: zero aggr scratch ----------------
__global__ void k_zero() {
    const int n4 = (N_NODES * D_F) / 4;
    float4* p = reinterpret_cast<float4*>(g_aggr);
    for (int i = blockIdx.x * blockDim.x + threadIdx.x; i < n4; i += gridDim.x * blockDim.x)
        p[i] = make_float4(0.f, 0.f, 0.f, 0.f);
}

// ---------------- kernel: pre-convert node-MLP weights to tf32 ----------------
__global__ void k_prep(const float* __restrict__ Wu1,
                       const float* __restrict__ Wu2,
                       const float* __restrict__ Wu3) {
    const int stride = gridDim.x * blockDim.x;
    const int t = blockIdx.x * blockDim.x + threadIdx.x;
    for (int i = t; i < D_U1 * D_CAT; i += stride) g_w1t[i] = tf32f(Wu1[i]);
    for (int i = t; i < D_U2 * D_U1; i += stride)  g_w2t[i] = tf32f(Wu2[i]);
    for (int i = t; i < D_OUT * D_U2; i += stride) g_w3t[i] = tf32f(Wu3[i]);
}

// ---------------- kernel: edge MLP (wmma tf32, 16 warps) + scatter-add ----------------
// warp (fw, eh): f-tile fw (16 f) x edge-half eh (64 e).
__global__ void __launch_bounds__(ETHREADS, 1)
k_edge(const float* __restrict__ edge_attr,
       const int* __restrict__ edge_index,
       const float* __restrict__ Wm1, const float* __restrict__ bm1,
       const float* __restrict__ Wm2, const float* __restrict__ bm2,
       const float* __restrict__ Wm3, const float* __restrict__ bm3)
{
    extern __shared__ char smem[];
    float* h1  = reinterpret_cast<float*>(smem + SB_H1);
    float* h2  = reinterpret_cast<float*>(smem + SB_H2);
    float* w3s = reinterpret_cast<float*>(smem + SB_W3);
    float* bm2m = reinterpret_cast<float*>(smem + SB_BM2);
    float* bm3m = reinterpret_cast<float*>(smem + SB_BM3);
    float* w1s = reinterpret_cast<float*>(smem + SB_W1);
    float* b1s = reinterpret_cast<float*>(smem + SB_B1);
    float* eab = reinterpret_cast<float*>(smem + SB_EA);
    int*   dsb = reinterpret_cast<int*>(smem + SB_DST);

    const int tid = threadIdx.x;
    const int w   = tid >> 5;
    const int l   = tid & 31;
    const int fw  = w & 7;      // f-tile 0..7
    const int eh  = w >> 3;     // edge-half 0..1
    const int f0  = fw * 16;
    const int ne0 = eh * 4;     // this warp's n-range: ne0..ne0+3

    for (int i = tid; i < 640; i += ETHREADS) w1s[i] = Wm1[i];
    if (tid < 128) b1s[tid] = bm1[tid];
    for (int i = tid; i < 128 * 16; i += ETHREADS) {
        const int f = i >> 4;
        bm2m[i] = bm2[f];
        bm3m[i] = bm3[f];
    }

    // ---- stage W2 tf32 via h1 region (139264 B avail), load persistent a2 ----
    wmma::fragment<wmma::matrix_a, 16, 16, 8, wmma::precision::tf32, wmma::row_major> a2[16];
    for (int i = tid; i < 128 * 128; i += ETHREADS) h1[i] = tf32f(Wm2[i]);
    __syncthreads();
#pragma unroll
    for (int kt = 0; kt < 16; kt++)
        wmma::load_matrix_sync(a2[kt], h1 + f0 * 128 + kt * 8, 128);
    __syncthreads();

    // ---- stage W3 tf32 permanently ----
    for (int i = tid; i < 128 * 128; i += ETHREADS) w3s[i] = tf32f(Wm3[i]);

    // ---- prefetch (depth 2) ----
    const int t0 = blockIdx.x;
    float4 ear = make_float4(0.f, 0.f, 0.f, 0.f);
    int    dsr = 0;
    if (tid < 160)
        reinterpret_cast<float4*>(eab)[tid] =
            reinterpret_cast<const float4*>(edge_attr + (long long)t0 * E_TILE * 5)[tid];
    if (tid < 128)
        dsb[tid] = edge_index[N_EDGES + t0 * E_TILE + tid];
    {
        const int t1 = (t0 + EGRID < N_TILES) ? t0 + EGRID : t0;
        if (tid < 160)
            ear = reinterpret_cast<const float4*>(edge_attr + (long long)t1 * E_TILE * 5)[tid];
        if (tid < 128)
            dsr = edge_index[N_EDGES + t1 * E_TILE + tid];
    }
    __syncthreads();

    // scatter mapping: 16 warps = 4 f-groups x 4 e-quarters
    const int fRow = (w & 3) * 32 + l;
    const int es0  = (w >> 2) * 32;

    int cur = 0;
    for (int tile = t0; tile < N_TILES; tile += EGRID) {
        const float* eas  = eab + cur * 640;
        const int*   dsti = dsb + cur * 128;

        // ---- layer 1: 5 -> 128, this thread: 16 f x 2 edges ----
        {
            const int e0 = eh * 64 + 2 * l;
            float a[10];
            const float2* ap = reinterpret_cast<const float2*>(&eas[e0 * 5]);
#pragma unroll
            for (int q = 0; q < 5; q++) {
                const float2 v = ap[q];
                a[2 * q] = v.x; a[2 * q + 1] = v.y;
            }
            // a[] holds 10 consecutive floats = edge e0 attrs (0..4), edge e0+1 attrs (5..9)
#pragma unroll
            for (int fi = 0; fi < 16; fi++) {
                const int f = f0 + fi;
                const float bb = b1s[f];
                float t0v = bb, t1v = bb;
#pragma unroll
                for (int j = 0; j < 5; j++) {
                    const float wv = w1s[f * 5 + j];
                    t0v = fmaf(wv, a[j], t0v);
                    t1v = fmaf(wv, a[5 + j], t1v);
                }
                *reinterpret_cast<float2*>(&h1[f * HP + e0]) =
                    make_float2(tf32f(leaky(t0v)), tf32f(leaky(t1v)));
            }
        }
        __syncthreads();

        // ---- layer 2: h2 = tf32(leaky(W2 @ h1 + b2)), a2 persistent, 2-wide ----
#pragma unroll
        for (int n = ne0; n < ne0 + 4; n += 2) {
            wmma::fragment<wmma::accumulator, 16, 16, 8, float> ac0, ac1;
            wmma::load_matrix_sync(ac0, bm2m + f0 * 16, 16, wmma::mem_row_major);
            ac1 = ac0;
#pragma unroll
            for (int kt = 0; kt < 16; kt++) {
                wmma::fragment<wmma::matrix_b, 16, 16, 8, wmma::precision::tf32, wmma::row_major> bf0, bf1;
                wmma::load_matrix_sync(bf0, h1 + kt * 8 * HP + n * 16, HP);
                wmma::load_matrix_sync(bf1, h1 + kt * 8 * HP + n * 16 + 16, HP);
                wmma::mma_sync(ac0, a2[kt], bf0, ac0);
                wmma::mma_sync(ac1, a2[kt], bf1, ac1);
            }
#pragma unroll
            for (int i = 0; i < ac0.num_elements; i++) {
                ac0.x[i] = tf32f(leaky(ac0.x[i]));
                ac1.x[i] = tf32f(leaky(ac1.x[i]));
            }
            wmma::store_matrix_sync(h2 + f0 * HP + n * 16, ac0, HP, wmma::mem_row_major);
            wmma::store_matrix_sync(h2 + f0 * HP + n * 16 + 16, ac1, HP, wmma::mem_row_major);
        }
        __syncthreads();

        // prefetch shuffle: regs -> other buffer, issue next LDG
        {
            const int nb = cur ^ 1;
            if (tid < 160) reinterpret_cast<float4*>(eab + nb * 640)[tid] = ear;
            if (tid < 128) dsb[nb * 128 + tid] = dsr;
            const int tn = tile + 2 * EGRID;
            const int tc = (tn < N_TILES) ? tn : t0;
            if (tid < 160)
                ear = reinterpret_cast<const float4*>(edge_attr + (long long)tc * E_TILE * 5)[tid];
            if (tid < 128)
                dsr = edge_index[N_EDGES + tc * E_TILE + tid];
        }

        // ---- layer 3: msg = W3 @ h2 + b3, A streamed from w3s, 2-wide ----
#pragma unroll
        for (int n = ne0; n < ne0 + 4; n += 2) {
            wmma::fragment<wmma::accumulator, 16, 16, 8, float> ac0, ac1;
            wmma::load_matrix_sync(ac0, bm3m + f0 * 16, 16, wmma::mem_row_major);
            ac1 = ac0;
#pragma unroll
            for (int kt = 0; kt < 16; kt++) {
                wmma::fragment<wmma::matrix_a, 16, 16, 8, wmma::precision::tf32, wmma::row_major> af;
                wmma::load_matrix_sync(af, w3s + f0 * 128 + kt * 8, 128);
                wmma::fragment<wmma::matrix_b, 16, 16, 8, wmma::precision::tf32, wmma::row_major> bf0, bf1;
                wmma::load_matrix_sync(bf0, h2 + kt * 8 * HP + n * 16, HP);
                wmma::load_matrix_sync(bf1, h2 + kt * 8 * HP + n * 16 + 16, HP);
                wmma::mma_sync(ac0, af, bf0, ac0);
                wmma::mma_sync(ac1, af, bf1, ac1);
            }
            wmma::store_matrix_sync(h1 + f0 * HP + n * 16, ac0, HP, wmma::mem_row_major);
            wmma::store_matrix_sync(h1 + f0 * HP + n * 16 + 16, ac1, HP, wmma::mem_row_major);
        }
        __syncthreads();

        // ---- scatter: coalesced red.global.add per edge (32 per thread) ----
        {
            const float* mrow = h1 + fRow * HP;
#pragma unroll 4
            for (int j = 0; j < 32; j++) {
                const int e = es0 + j;
                const int d = dsti[e];
                red_f32(&g_aggr[(long long)d * D_F + fRow], mrow[e]);
            }
        }
        __syncthreads();
        cur ^= 1;
    }
}

// ---------------- kernel: LayerNorm over concat(x, aggr), tf32 output ----------------
__global__ void k_ln(const float* __restrict__ x,
                     const float* __restrict__ ln_g,
                     const float* __restrict__ ln_b)
{
    const int node = (blockIdx.x * blockDim.x + threadIdx.x) >> 5;
    const int lane = threadIdx.x & 31;
    if (node >= N_NODES) return;

    const float* xr = x      + (long long)node * D_F;
    const float* ar = g_aggr + (long long)node * D_F;
    float v[8];
#pragma unroll
    for (int i = 0; i < 4; i++) v[i]     = xr[lane + 32 * i];
#pragma unroll
    for (int i = 0; i < 4; i++) v[4 + i] = ar[lane + 32 * i];

    float s = 0.f;
#pragma unroll
    for (int i = 0; i < 8; i++) s += v[i];
#pragma unroll
    for (int o = 16; o > 0; o >>= 1) s += __shfl_xor_sync(0xffffffffu, s, o);
    const float mu = s * (1.0f / 256.0f);

    float q = 0.f;
#pragma unroll
    for (int i = 0; i < 8; i++) { const float d = v[i] - mu; q += d * d; }
#pragma unroll
    for (int o = 16; o > 0; o >>= 1) q += __shfl_xor_sync(0xffffffffu, q, o);
    const float rstd = rsqrtf(q * (1.0f / 256.0f) + 1e-5f);

    float* out = g_nrm + (long long)node * D_CAT;
#pragma unroll
    for (int i = 0; i < 8; i++) {
        const int c = (i < 4) ? (lane + 32 * i) : (128 + lane + 32 * (i - 4));
        out[c] = tf32f((v[i] - mu) * rstd * ln_g[c] + ln_b[c]);
    }
}

// ---------------- kernel: wmma tf32 GEMM, cp.async double-buffered (R12) ----------------
__global__ void __launch_bounds__(256)
k_wgemm(const float* __restrict__ A, const float* __restrict__ B,
        const float* __restrict__ bias, float* __restrict__ C,
        int M, int N, int K, int doLeaky, int outCvt)
{
    __shared__ float As[2][64 * 36];
    __shared__ float Bs[2][64 * 36];
    __shared__ float bmat[16 * 68];

    const int tid = threadIdx.x;
    const int w  = tid >> 5;
    const int wm = w >> 2;    // 0..1
    const int wn = w & 3;     // 0..3
    int m0 = blockIdx.x * 64; if (m0 > M - 64) m0 = M - 64;
    int n0 = blockIdx.y * 64; if (n0 > N - 64) n0 = N - 64;

    for (int i = tid; i < 16 * 64; i += 256) {
        const int r = i >> 6, c = i & 63;
        bmat[r * 68 + c] = bias[n0 + c];
    }
    __syncthreads();

    wmma::fragment<wmma::accumulator, 16, 16, 8, float> acc0, acc1;
    wmma::load_matrix_sync(acc0, bmat + wn * 16, 68, wmma::mem_row_major);
    acc1 = acc0;

    const int mm = tid >> 5;
    const int kk = tid & 31;
    const int nChunks = (K + 31) / 32;

    auto stage = [&](int c, int b) {
#pragma unroll
        for (int r = 0; r < 8; r++) {
            const int row = mm + r * 8;
            const int ka = c * 32 + kk;
            float* dA = &As[b][row * 36 + kk];
            float* dB = &Bs[b][row * 36 + kk];
            if (ka < K) {
                cp_async4((unsigned)__cvta_generic_to_shared(dA),
                          A + (long long)(m0 + row) * K + ka);
                cp_async4((unsigned)__cvta_generic_to_shared(dB),
                          B + (long long)(n0 + row) * K + ka);
            } else {
                *dA = 0.f;
                *dB = 0.f;
            }
        }
    };

    stage(0, 0);
    CP_COMMIT();

    for (int c = 0; c < nChunks; c++) {
        const int buf = c & 1;
        if (c + 1 < nChunks) {
            stage(c + 1, buf ^ 1);
            CP_COMMIT();
            CP_WAIT(1);
        } else {
            CP_WAIT(0);
        }
        __syncthreads();
#pragma unroll
        for (int kt = 0; kt < 4; kt++) {
            wmma::fragment<wmma::matrix_a, 16, 16, 8, wmma::precision::tf32, wmma::row_major> af0, af1;
            wmma::fragment<wmma::matrix_b, 16, 16, 8, wmma::precision::tf32, wmma::col_major> bf;
            wmma::load_matrix_sync(af0, &As[buf][(wm * 32) * 36 + kt * 8], 36);
            wmma::load_matrix_sync(af1, &As[buf][(wm * 32 + 16) * 36 + kt * 8], 36);
            wmma::load_matrix_sync(bf,  &Bs[buf][(wn * 16) * 36 + kt * 8], 36);
            wmma::mma_sync(acc0, af0, bf, acc0);
            wmma::mma_sync(acc1, af1, bf, acc1);
        }
        __syncthreads();
    }

#pragma unroll
    for (int i = 0; i < acc0.num_elements; i++) {
        float v0 = acc0.x[i], v1 = acc1.x[i];
        if (doLeaky) { v0 = leaky(v0); v1 = leaky(v1); }
        if (outCvt)  { v0 = tf32f(v0); v1 = tf32f(v1); }
        acc0.x[i] = v0; acc1.x[i] = v1;
    }
    wmma::store_matrix_sync(C + (long long)(m0 + wm * 32) * N + n0 + wn * 16,
                            acc0, N, wmma::mem_row_major);
    wmma::store_matrix_sync(C + (long long)(m0 + wm * 32 + 16) * N + n0 + wn * 16,
                            acc1, N, wmma::mem_row_major);
}

// ---------------- launch ----------------
extern "C" void kernel_launch(void* const* d_in, const int* in_sizes, int n_in,
                              void* d_out, int out_size)
{
    const float* x          = (const float*)d_in[0];
    const int*   edge_index = (const int*)d_in[1];
    const float* edge_attr  = (const float*)d_in[2];
    const float* Wm1 = (const float*)d_in[3];
    const float* bm1 = (const float*)d_in[4];
    const float* Wm2 = (const float*)d_in[5];
    const float* bm2 = (const float*)d_in[6];
    const float* Wm3 = (const float*)d_in[7];
    const float* bm3 = (const float*)d_in[8];
    const float* ln_g = (const float*)d_in[9];
    const float* ln_b = (const float*)d_in[10];
    const float* Wu1 = (const float*)d_in[11];
    const float* bu1 = (const float*)d_in[12];
    const float* Wu2 = (const float*)d_in[13];
    const float* bu2 = (const float*)d_in[14];
    const float* Wu3 = (const float*)d_in[15];
    const float* bu3 = (const float*)d_in[16];
    float* out = (float*)d_out;

    void *p_nrm = nullptr, *p_u1 = nullptr, *p_u2 = nullptr;
    void *p_w1 = nullptr, *p_w2 = nullptr, *p_w3 = nullptr;
    cudaGetSymbolAddress(&p_nrm, g_nrm);
    cudaGetSymbolAddress(&p_u1,  g_u1);
    cudaGetSymbolAddress(&p_u2,  g_u2);
    cudaGetSymbolAddress(&p_w1,  g_w1t);
    cudaGetSymbolAddress(&p_w2,  g_w2t);
    cudaGetSymbolAddress(&p_w3,  g_w3t);

    cudaFuncSetAttribute(k_edge, cudaFuncAttributeMaxDynamicSharedMemorySize, EDGE_SMEM_BYTES);

    k_zero<<<2048, 256>>>();
    k_prep<<<64, 256>>>(Wu1, Wu2, Wu3);
    k_nop<<<1, 32>>>();

    k_edge<<<EGRID, ETHREADS, EDGE_SMEM_BYTES>>>(edge_attr, edge_index,
                                                 Wm1, bm1, Wm2, bm2, Wm3, bm3);

    k_ln<<<(N_NODES * 32 + 255) / 256, 256>>>(x, ln_g, ln_b);

    dim3 g1((N_NODES + 63) / 64, (D_U1 + 63) / 64);
    k_wgemm<<<g1, 256>>>((const float*)p_nrm, (const float*)p_w1, bu1, (float*)p_u1,
                         N_NODES, D_U1, D_CAT, 1, 1);

    dim3 g2((N_NODES + 63) / 64, (D_U2 + 63) / 64);
    k_wgemm<<<g2, 256>>>((const float*)p_u1, (const float*)p_w2, bu2, (float*)p_u2,
                         N_NODES, D_U2, D_U1, 1, 1);

    dim3 g3((N_NODES + 63) / 64, (D_OUT + 63) / 64);
    k_wgemm<<<g3, 256>>>((const float*)p_u2, (const float*)p_w3, bu3, out,
                         N_NODES, D_OUT, D_U2, 0, 0);
}

// round 15
// speedup vs baseline: 1.3427x; 1.3427x over previous
#include <cuda_runtime.h>
#include <mma.h>

using namespace nvcuda;

#define N_NODES 100000
#define N_EDGES 1600000
#define D_F     128
#define D_CAT   256
#define D_U1    214
#define D_U2    172
#define D_OUT   128

#define E_TILE   128
#define N_TILES  (N_EDGES / E_TILE)   // 12500
#define EGRID    148
#define HP 136                        // h pitch (floats)

// ---- k_edge dynamic smem byte offsets (R12-measured layout) ----
#define SB_H1   0                     // h1 [128][HP] : 69632 B
#define SB_H2   69632                 // h2 [128][HP] : 69632 B
#define SB_WST  139264                // weight staging / bias mats : 65536 B
#define SB_W1   204800                // 640 floats
#define SB_B1   207360
#define SB_B2   207872
#define SB_B3   208384
#define SB_EA   208896                // 2 x 640 floats
#define SB_DST  214016                // 2 x 128 ints
#define EDGE_SMEM_BYTES 215040

// ---------------- scratch ----------------
__device__ float g_aggr[N_NODES * D_F];
__device__ float g_nrm [N_NODES * D_CAT];
__device__ float g_u1  [N_NODES * D_U1];
__device__ float g_u2  [N_NODES * D_U2];
__device__ float g_w1t [D_U1 * D_CAT];
__device__ float g_w2t [D_U2 * D_U1];
__device__ float g_w3t [D_OUT * D_U2];

// ---------------- helpers ----------------
__device__ __forceinline__ float leaky(float v) { return v > 0.f ? v : 0.01f * v; }

__device__ __forceinline__ float tf32f(float x) {
    unsigned r; asm("cvt.rna.tf32.f32 %0, %1;" : "=r"(r) : "f"(x));
    return __uint_as_float(r);
}
__device__ __forceinline__ void red_f32(float* p, float v) {
    asm volatile("red.global.add.f32 [%0], %1;" :: "l"(p), "f"(v) : "memory");
}
__device__ __forceinline__ void cp_async4(unsigned saddr, const void* g) {
    asm volatile("cp.async.ca.shared.global [%0], [%1], 4;" :: "r"(saddr), "l"(g));
}
#define CP_COMMIT() asm volatile("cp.async.commit_group;" ::: "memory")
#define CP_WAIT(n)  asm volatile("cp.async.wait_group %0;" :: "n"(n) : "memory")

// ---------------- kernel: nop (ncu capture alignment) ----------------
__global__ void k_nop() {}

// ---------------- kernel: zero aggr scratch ----------------
__global__ void k_zero() {
    const int n4 = (N_NODES * D_F) / 4;
    float4* p = reinterpret_cast<float4*>(g_aggr);
    for (int i = blockIdx.x * blockDim.x + threadIdx.x; i < n4; i += gridDim.x * blockDim.x)
        p[i] = make_float4(0.f, 0.f, 0.f, 0.f);
}

// ---------------- kernel: pre-convert node-MLP weights to tf32 ----------------
__global__ void k_prep(const float* __restrict__ Wu1,
                       const float* __restrict__ Wu2,
                       const float* __restrict__ Wu3) {
    const int stride = gridDim.x * blockDim.x;
    const int t = blockIdx.x * blockDim.x + threadIdx.x;
    for (int i = t; i < D_U1 * D_CAT; i += stride) g_w1t[i] = tf32f(Wu1[i]);
    for (int i = t; i < D_U2 * D_U1; i += stride)  g_w2t[i] = tf32f(Wu2[i]);
    for (int i = t; i < D_OUT * D_U2; i += stride) g_w3t[i] = tf32f(Wu3[i]);
}

// ---------------- kernel: edge MLP (wmma tf32) — R12-measured best, verbatim ----------------
__global__ void __launch_bounds__(256, 1)
k_edge(const float* __restrict__ edge_attr,
       const int* __restrict__ edge_index,
       const float* __restrict__ Wm1, const float* __restrict__ bm1,
       const float* __restrict__ Wm2, const float* __restrict__ bm2,
       const float* __restrict__ Wm3, const float* __restrict__ bm3)
{
    extern __shared__ char smem[];
    float* h1  = reinterpret_cast<float*>(smem + SB_H1);
    float* h2  = reinterpret_cast<float*>(smem + SB_H2);
    float* wst = reinterpret_cast<float*>(smem + SB_WST);
    float* w1s = reinterpret_cast<float*>(smem + SB_W1);
    float* b1s = reinterpret_cast<float*>(smem + SB_B1);
    float* b2s = reinterpret_cast<float*>(smem + SB_B2);
    float* b3s = reinterpret_cast<float*>(smem + SB_B3);
    float* eab = reinterpret_cast<float*>(smem + SB_EA);
    int*   dsb = reinterpret_cast<int*>(smem + SB_DST);

    const int tid = threadIdx.x;
    const int w   = tid >> 5;
    const int l   = tid & 31;
    const int f0  = w * 16;

    for (int i = tid; i < 640; i += 256) w1s[i] = Wm1[i];
    if (tid < 128) { b1s[tid] = bm1[tid]; b2s[tid] = bm2[tid]; b3s[tid] = bm3[tid]; }

    wmma::fragment<wmma::matrix_a, 16, 16, 8, wmma::precision::tf32, wmma::row_major> a2[16], a3[16];
    for (int i = tid; i < 128 * 128; i += 256) wst[i] = tf32f(Wm2[i]);
    __syncthreads();
#pragma unroll
    for (int kt = 0; kt < 16; kt++)
        wmma::load_matrix_sync(a2[kt], wst + f0 * 128 + kt * 8, 128);
    __syncthreads();
    for (int i = tid; i < 128 * 128; i += 256) wst[i] = tf32f(Wm3[i]);
    __syncthreads();
#pragma unroll
    for (int kt = 0; kt < 16; kt++)
        wmma::load_matrix_sync(a3[kt], wst + f0 * 128 + kt * 8, 128);
    __syncthreads();

    float* bm2m = wst;          // [128][16]
    float* bm3m = wst + 2048;   // [128][16]
    for (int i = tid; i < 128 * 16; i += 256) {
        const int f = i >> 4;
        bm2m[i] = b2s[f];
        bm3m[i] = b3s[f];
    }
    __syncthreads();
    wmma::fragment<wmma::accumulator, 16, 16, 8, float> ab2, ab3;
    wmma::load_matrix_sync(ab2, bm2m + f0 * 16, 16, wmma::mem_row_major);
    wmma::load_matrix_sync(ab3, bm3m + f0 * 16, 16, wmma::mem_row_major);

    const int t0 = blockIdx.x;
    float4 ear = make_float4(0.f, 0.f, 0.f, 0.f);
    int    dsr = 0;
    if (tid < 160)
        reinterpret_cast<float4*>(eab)[tid] =
            reinterpret_cast<const float4*>(edge_attr + (long long)t0 * E_TILE * 5)[tid];
    if (tid < 128)
        dsb[tid] = edge_index[N_EDGES + t0 * E_TILE + tid];
    {
        const int t1 = (t0 + EGRID < N_TILES) ? t0 + EGRID : t0;
        if (tid < 160)
            ear = reinterpret_cast<const float4*>(edge_attr + (long long)t1 * E_TILE * 5)[tid];
        if (tid < 128)
            dsr = edge_index[N_EDGES + t1 * E_TILE + tid];
    }
    __syncthreads();

    const int fRow = (w & 3) * 32 + l;
    const int es0  = (w >> 2) * 64;

    int cur = 0;
    for (int tile = t0; tile < N_TILES; tile += EGRID) {
        const float* eas  = eab + cur * 640;
        const int*   dsti = dsb + cur * 128;

        // ---- layer 1: 5 -> 128, write h1[k=f][e] (tf32) ----
        {
            float a[20];
            const float4* ap = reinterpret_cast<const float4*>(&eas[(4 * l) * 5]);
#pragma unroll
            for (int q = 0; q < 5; q++) {
                const float4 v = ap[q];
                a[4*q] = v.x; a[4*q+1] = v.y; a[4*q+2] = v.z; a[4*q+3] = v.w;
            }
#pragma unroll
            for (int fi = 0; fi < 16; fi++) {
                const int f = f0 + fi;
                const float bb = b1s[f];
                float v[4];
#pragma unroll
                for (int ei = 0; ei < 4; ei++) {
                    float t = bb;
#pragma unroll
                    for (int j = 0; j < 5; j++)
                        t = fmaf(w1s[f * 5 + j], a[ei * 5 + j], t);
                    v[ei] = tf32f(leaky(t));
                }
                *reinterpret_cast<float4*>(&h1[f * HP + 4 * l]) =
                    make_float4(v[0], v[1], v[2], v[3]);
            }
        }
        __syncthreads();

        // ---- layer 2: h2 = tf32(leaky(W2 @ h1 + b2)), 2-wide n interleave ----
#pragma unroll 1
        for (int n = 0; n < 8; n += 2) {
            wmma::fragment<wmma::accumulator, 16, 16, 8, float> ac0 = ab2, ac1 = ab2;
#pragma unroll
            for (int kt = 0; kt < 16; kt++) {
                wmma::fragment<wmma::matrix_b, 16, 16, 8, wmma::precision::tf32, wmma::row_major> bf0, bf1;
                wmma::load_matrix_sync(bf0, h1 + kt * 8 * HP + n * 16, HP);
                wmma::load_matrix_sync(bf1, h1 + kt * 8 * HP + n * 16 + 16, HP);
                wmma::mma_sync(ac0, a2[kt], bf0, ac0);
                wmma::mma_sync(ac1, a2[kt], bf1, ac1);
            }
#pragma unroll
            for (int i = 0; i < ac0.num_elements; i++) {
                ac0.x[i] = tf32f(leaky(ac0.x[i]));
                ac1.x[i] = tf32f(leaky(ac1.x[i]));
            }
            wmma::store_matrix_sync(h2 + f0 * HP + n * 16, ac0, HP, wmma::mem_row_major);
            wmma::store_matrix_sync(h2 + f0 * HP + n * 16 + 16, ac1, HP, wmma::mem_row_major);
        }
        __syncthreads();

        // prefetch shuffle: regs -> other buffer, issue next LDG
        {
            const int nb = cur ^ 1;
            if (tid < 160) reinterpret_cast<float4*>(eab + nb * 640)[tid] = ear;
            if (tid < 128) dsb[nb * 128 + tid] = dsr;
            const int tn = tile + 2 * EGRID;
            const int tc = (tn < N_TILES) ? tn : t0;
            if (tid < 160)
                ear = reinterpret_cast<const float4*>(edge_attr + (long long)tc * E_TILE * 5)[tid];
            if (tid < 128)
                dsr = edge_index[N_EDGES + tc * E_TILE + tid];
        }

        // ---- layer 3: msg = W3 @ h2 + b3, store into h1 ----
#pragma unroll 1
        for (int n = 0; n < 8; n += 2) {
            wmma::fragment<wmma::accumulator, 16, 16, 8, float> ac0 = ab3, ac1 = ab3;
#pragma unroll
            for (int kt = 0; kt < 16; kt++) {
                wmma::fragment<wmma::matrix_b, 16, 16, 8, wmma::precision::tf32, wmma::row_major> bf0, bf1;
                wmma::load_matrix_sync(bf0, h2 + kt * 8 * HP + n * 16, HP);
                wmma::load_matrix_sync(bf1, h2 + kt * 8 * HP + n * 16 + 16, HP);
                wmma::mma_sync(ac0, a3[kt], bf0, ac0);
                wmma::mma_sync(ac1, a3[kt], bf1, ac1);
            }
            wmma::store_matrix_sync(h1 + f0 * HP + n * 16, ac0, HP, wmma::mem_row_major);
            wmma::store_matrix_sync(h1 + f0 * HP + n * 16 + 16, ac1, HP, wmma::mem_row_major);
        }
        __syncthreads();

        // ---- scatter: coalesced red.global.add per edge ----
        {
            const float* mrow = h1 + fRow * HP;
#pragma unroll 4
            for (int j = 0; j < 64; j++) {
                const int e = es0 + j;
                const int d = dsti[e];
                red_f32(&g_aggr[(long long)d * D_F + fRow], mrow[e]);
            }
        }
        __syncthreads();
        cur ^= 1;
    }
}

// ---------------- kernel: LayerNorm over concat(x, aggr), tf32 output ----------------
__global__ void k_ln(const float* __restrict__ x,
                     const float* __restrict__ ln_g,
                     const float* __restrict__ ln_b)
{
    const int node = (blockIdx.x * blockDim.x + threadIdx.x) >> 5;
    const int lane = threadIdx.x & 31;
    if (node >= N_NODES) return;

    const float* xr = x      + (long long)node * D_F;
    const float* ar = g_aggr + (long long)node * D_F;
    float v[8];
#pragma unroll
    for (int i = 0; i < 4; i++) v[i]     = xr[lane + 32 * i];
#pragma unroll
    for (int i = 0; i < 4; i++) v[4 + i] = ar[lane + 32 * i];

    float s = 0.f;
#pragma unroll
    for (int i = 0; i < 8; i++) s += v[i];
#pragma unroll
    for (int o = 16; o > 0; o >>= 1) s += __shfl_xor_sync(0xffffffffu, s, o);
    const float mu = s * (1.0f / 256.0f);

    float q = 0.f;
#pragma unroll
    for (int i = 0; i < 8; i++) { const float d = v[i] - mu; q += d * d; }
#pragma unroll
    for (int o = 16; o > 0; o >>= 1) q += __shfl_xor_sync(0xffffffffu, q, o);
    const float rstd = rsqrtf(q * (1.0f / 256.0f) + 1e-5f);

    float* out = g_nrm + (long long)node * D_CAT;
#pragma unroll
    for (int i = 0; i < 8; i++) {
        const int c = (i < 4) ? (lane + 32 * i) : (128 + lane + 32 * (i - 4));
        out[c] = tf32f((v[i] - mu) * rstd * ln_g[c] + ln_b[c]);
    }
}

// ---------------- kernel: wmma tf32 GEMM, cp.async double-buffered ----------------
// 128m x 64n block tile, 8 warps (4m x 2n), warp tile 32m x 32n (2x2 acc frags):
// 1.0 frag-loads per mma, 4 independent HMMA chains.
__global__ void __launch_bounds__(256)
k_wgemm(const float* __restrict__ A, const float* __restrict__ B,
        const float* __restrict__ bias, float* __restrict__ C,
        int M, int N, int K, int doLeaky, int outCvt)
{
    __shared__ float As[2][128 * 36];
    __shared__ float Bs[2][64 * 36];
    __shared__ float bmat[16 * 68];

    const int tid = threadIdx.x;
    const int w  = tid >> 5;
    const int wm = w >> 1;    // 0..3
    const int wn = w & 1;     // 0..1
    int m0 = blockIdx.x * 128; if (m0 > M - 128) m0 = M - 128;
    int n0 = blockIdx.y * 64;  if (n0 > N - 64)  n0 = N - 64;

    for (int i = tid; i < 16 * 64; i += 256) {
        const int r = i >> 6, c = i & 63;
        bmat[r * 68 + c] = bias[n0 + c];
    }
    __syncthreads();

    wmma::fragment<wmma::accumulator, 16, 16, 8, float> acc[2][2];
#pragma unroll
    for (int j = 0; j < 2; j++) {
        wmma::load_matrix_sync(acc[0][j], bmat + wn * 32 + j * 16, 68, wmma::mem_row_major);
        acc[1][j] = acc[0][j];
    }

    const int mm = tid >> 5;
    const int kk = tid & 31;
    const int nChunks = (K + 31) / 32;

    // stage chunk c into buffer b: A 128 rows (16/thread), B 64 rows (8/thread)
    auto stage = [&](int c, int b) {
        const int ka = c * 32 + kk;
        const bool kok = (ka < K);
#pragma unroll
        for (int r = 0; r < 16; r++) {
            const int row = mm + r * 8;
            float* dA = &As[b][row * 36 + kk];
            if (kok) cp_async4((unsigned)__cvta_generic_to_shared(dA),
                               A + (long long)(m0 + row) * K + ka);
            else     *dA = 0.f;
        }
#pragma unroll
        for (int r = 0; r < 8; r++) {
            const int row = mm + r * 8;
            float* dB = &Bs[b][row * 36 + kk];
            if (kok) cp_async4((unsigned)__cvta_generic_to_shared(dB),
                               B + (long long)(n0 + row) * K + ka);
            else     *dB = 0.f;
        }
    };

    stage(0, 0);
    CP_COMMIT();

    for (int c = 0; c < nChunks; c++) {
        const int buf = c & 1;
        if (c + 1 < nChunks) {
            stage(c + 1, buf ^ 1);
            CP_COMMIT();
            CP_WAIT(1);
        } else {
            CP_WAIT(0);
        }
        __syncthreads();
#pragma unroll
        for (int kt = 0; kt < 4; kt++) {
            wmma::fragment<wmma::matrix_a, 16, 16, 8, wmma::precision::tf32, wmma::row_major> af[2];
            wmma::fragment<wmma::matrix_b, 16, 16, 8, wmma::precision::tf32, wmma::col_major> bf[2];
#pragma unroll
            for (int i = 0; i < 2; i++)
                wmma::load_matrix_sync(af[i], &As[buf][(wm * 32 + i * 16) * 36 + kt * 8], 36);
#pragma unroll
            for (int j = 0; j < 2; j++)
                wmma::load_matrix_sync(bf[j], &Bs[buf][(wn * 32 + j * 16) * 36 + kt * 8], 36);
#pragma unroll
            for (int i = 0; i < 2; i++)
#pragma unroll
                for (int j = 0; j < 2; j++)
                    wmma::mma_sync(acc[i][j], af[i], bf[j], acc[i][j]);
        }
        __syncthreads();
    }

#pragma unroll
    for (int i = 0; i < 2; i++)
#pragma unroll
        for (int j = 0; j < 2; j++) {
#pragma unroll
            for (int e = 0; e < acc[i][j].num_elements; e++) {
                float v = acc[i][j].x[e];
                if (doLeaky) v = leaky(v);
                if (outCvt)  v = tf32f(v);
                acc[i][j].x[e] = v;
            }
            wmma::store_matrix_sync(
                C + (long long)(m0 + wm * 32 + i * 16) * N + n0 + wn * 32 + j * 16,
                acc[i][j], N, wmma::mem_row_major);
        }
}

// ---------------- launch ----------------
extern "C" void kernel_launch(void* const* d_in, const int* in_sizes, int n_in,
                              void* d_out, int out_size)
{
    const float* x          = (const float*)d_in[0];
    const int*   edge_index = (const int*)d_in[1];
    const float* edge_attr  = (const float*)d_in[2];
    const float* Wm1 = (const float*)d_in[3];
    const float* bm1 = (const float*)d_in[4];
    const float* Wm2 = (const float*)d_in[5];
    const float* bm2 = (const float*)d_in[6];
    const float* Wm3 = (const float*)d_in[7];
    const float* bm3 = (const float*)d_in[8];
    const float* ln_g = (const float*)d_in[9];
    const float* ln_b = (const float*)d_in[10];
    const float* Wu1 = (const float*)d_in[11];
    const float* bu1 = (const float*)d_in[12];
    const float* Wu2 = (const float*)d_in[13];
    const float* bu2 = (const float*)d_in[14];
    const float* Wu3 = (const float*)d_in[15];
    const float* bu3 = (const float*)d_in[16];
    float* out = (float*)d_out;

    void *p_nrm = nullptr, *p_u1 = nullptr, *p_u2 = nullptr;
    void *p_w1 = nullptr, *p_w2 = nullptr, *p_w3 = nullptr;
    cudaGetSymbolAddress(&p_nrm, g_nrm);
    cudaGetSymbolAddress(&p_u1,  g_u1);
    cudaGetSymbolAddress(&p_u2,  g_u2);
    cudaGetSymbolAddress(&p_w1,  g_w1t);
    cudaGetSymbolAddress(&p_w2,  g_w2t);
    cudaGetSymbolAddress(&p_w3,  g_w3t);

    cudaFuncSetAttribute(k_edge, cudaFuncAttributeMaxDynamicSharedMemorySize, EDGE_SMEM_BYTES);

    k_zero<<<2048, 256>>>();
    k_prep<<<64, 256>>>(Wu1, Wu2, Wu3);
    k_nop<<<1, 32>>>();

    k_edge<<<EGRID, 256, EDGE_SMEM_BYTES>>>(edge_attr, edge_index,
                                            Wm1, bm1, Wm2, bm2, Wm3, bm3);

    k_ln<<<(N_NODES * 32 + 255) / 256, 256>>>(x, ln_g, ln_b);

    dim3 g1((N_NODES + 127) / 128, (D_U1 + 63) / 64);
    k_wgemm<<<g1, 256>>>((const float*)p_nrm, (const float*)p_w1, bu1, (float*)p_u1,
                         N_NODES, D_U1, D_CAT, 1, 1);

    dim3 g2((N_NODES + 127) / 128, (D_U2 + 63) / 64);
    k_wgemm<<<g2, 256>>>((const float*)p_u1, (const float*)p_w2, bu2, (float*)p_u2,
                         N_NODES, D_U2, D_U1, 1, 1);

    dim3 g3((N_NODES + 127) / 128, (D_OUT + 63) / 64);
    k_wgemm<<<g3, 256>>>((const float*)p_u2, (const float*)p_w3, bu3, out,
                         N_NODES, D_OUT, D_U2, 0, 0);
}

// round 16
// speedup vs baseline: 2.3760x; 1.7696x over previous
#include <cuda_runtime.h>
#include <cuda_fp16.h>
#include <mma.h>

using namespace nvcuda;

#define N_NODES 100000
#define N_EDGES 1600000
#define D_F     128
#define D_CAT   256
#define D_U1    214
#define D_U2    172
#define D_OUT   128

#define E_TILE   128
#define N_TILES  (N_EDGES / E_TILE)   // 12500
#define EGRID    148
#define HP  136                       // float pitch (mf)
#define HPH 144                       // half pitch (h1h/h2h)

// ---- k_edge dynamic smem byte offsets ----
#define SB_MF   0                     // float [128][HP] : 69632 B (layer-2/3 fp32 out)
#define SB_H1H  69632                 // half [128][HPH] : 36864 B
#define SB_H2H  106496                // half [128][HPH] : 36864 B
#define SB_WS   143360                // fp16 weight staging 32768 B (then bias mats)
#define SB_W1   176128                // 640 floats : 2560 B
#define SB_B1   178688                // 512 B
#define SB_B2   179200
#define SB_B3   179712
#define SB_EA   180224                // 2 x 640 floats : 5120 B
#define SB_DST  185344                // 2 x 128 ints : 1024 B
#define EDGE_SMEM_BYTES 186368

// ---------------- scratch ----------------
__device__ float g_aggr[N_NODES * D_F];
__device__ float g_nrm [N_NODES * D_CAT];
__device__ float g_u1  [N_NODES * D_U1];
__device__ float g_u2  [N_NODES * D_U2];
__device__ float g_w1t [D_U1 * D_CAT];
__device__ float g_w2t [D_U2 * D_U1];
__device__ float g_w3t [D_OUT * D_U2];

// ---------------- helpers ----------------
__device__ __forceinline__ float leaky(float v) { return v > 0.f ? v : 0.01f * v; }

__device__ __forceinline__ float tf32f(float x) {
    unsigned r; asm("cvt.rna.tf32.f32 %0, %1;" : "=r"(r) : "f"(x));
    return __uint_as_float(r);
}
__device__ __forceinline__ void red_f32(float* p, float v) {
    asm volatile("red.global.add.f32 [%0], %1;" :: "l"(p), "f"(v) : "memory");
}
__device__ __forceinline__ void cp_async4(unsigned saddr, const void* g) {
    asm volatile("cp.async.ca.shared.global [%0], [%1], 4;" :: "r"(saddr), "l"(g));
}
#define CP_COMMIT() asm volatile("cp.async.commit_group;" ::: "memory")
#define CP_WAIT(n)  asm volatile("cp.async.wait_group %0;" :: "n"(n) : "memory")

// ---------------- kernel: nop (ncu capture alignment) ----------------
__global__ void k_nop() {}

// ---------------- kernel: zero aggr scratch ----------------
__global__ void k_zero() {
    const int n4 = (N_NODES * D_F) / 4;
    float4* p = reinterpret_cast<float4*>(g_aggr);
    for (int i = blockIdx.x * blockDim.x + threadIdx.x; i < n4; i += gridDim.x * blockDim.x)
        p[i] = make_float4(0.f, 0.f, 0.f, 0.f);
}

// ---------------- kernel: pre-convert node-MLP weights to tf32 ----------------
__global__ void k_prep(const float* __restrict__ Wu1,
                       const float* __restrict__ Wu2,
                       const float* __restrict__ Wu3) {
    const int stride = gridDim.x * blockDim.x;
    const int t = blockIdx.x * blockDim.x + threadIdx.x;
    for (int i = t; i < D_U1 * D_CAT; i += stride) g_w1t[i] = tf32f(Wu1[i]);
    for (int i = t; i < D_U2 * D_U1; i += stride)  g_w2t[i] = tf32f(Wu2[i]);
    for (int i = t; i < D_OUT * D_U2; i += stride) g_w3t[i] = tf32f(Wu3[i]);
}

// ---------------- kernel: edge MLP (wmma fp16 m16n16k16, fp32 acc) ----------------
__global__ void __launch_bounds__(256, 1)
k_edge(const float* __restrict__ edge_attr,
       const int* __restrict__ edge_index,
       const float* __restrict__ Wm1, const float* __restrict__ bm1,
       const float* __restrict__ Wm2, const float* __restrict__ bm2,
       const float* __restrict__ Wm3, const float* __restrict__ bm3)
{
    extern __shared__ char smem[];
    float* mf   = reinterpret_cast<float*>(smem + SB_MF);
    __half* h1h = reinterpret_cast<__half*>(smem + SB_H1H);
    __half* h2h = reinterpret_cast<__half*>(smem + SB_H2H);
    __half* ws  = reinterpret_cast<__half*>(smem + SB_WS);
    float* w1s = reinterpret_cast<float*>(smem + SB_W1);
    float* b1s = reinterpret_cast<float*>(smem + SB_B1);
    float* b2s = reinterpret_cast<float*>(smem + SB_B2);
    float* b3s = reinterpret_cast<float*>(smem + SB_B3);
    float* eab = reinterpret_cast<float*>(smem + SB_EA);
    int*   dsb = reinterpret_cast<int*>(smem + SB_DST);

    const int tid = threadIdx.x;
    const int w   = tid >> 5;
    const int l   = tid & 31;
    const int f0  = w * 16;

    for (int i = tid; i < 640; i += 256) w1s[i] = Wm1[i];
    if (tid < 128) { b1s[tid] = bm1[tid]; b2s[tid] = bm2[tid]; b3s[tid] = bm3[tid]; }

    // ---- stage W2 fp16, load persistent a2 (8 frags) ----
    wmma::fragment<wmma::matrix_a, 16, 16, 16, __half, wmma::row_major> a2[8], a3[8];
    for (int i = tid; i < 128 * 128; i += 256) ws[i] = __float2half_rn(Wm2[i]);
    __syncthreads();
#pragma unroll
    for (int kt = 0; kt < 8; kt++)
        wmma::load_matrix_sync(a2[kt], ws + f0 * 128 + kt * 16, 128);
    __syncthreads();
    for (int i = tid; i < 128 * 128; i += 256) ws[i] = __float2half_rn(Wm3[i]);
    __syncthreads();
#pragma unroll
    for (int kt = 0; kt < 8; kt++)
        wmma::load_matrix_sync(a3[kt], ws + f0 * 128 + kt * 16, 128);
    __syncthreads();

    // ---- bias accumulator fragments (staged in ws region as float) ----
    float* bm2m = reinterpret_cast<float*>(ws);          // [128][16]
    float* bm3m = bm2m + 2048;                           // [128][16]
    for (int i = tid; i < 128 * 16; i += 256) {
        const int f = i >> 4;
        bm2m[i] = b2s[f];
        bm3m[i] = b3s[f];
    }
    __syncthreads();
    wmma::fragment<wmma::accumulator, 16, 16, 16, float> ab2, ab3;
    wmma::load_matrix_sync(ab2, bm2m + f0 * 16, 16, wmma::mem_row_major);
    wmma::load_matrix_sync(ab3, bm3m + f0 * 16, 16, wmma::mem_row_major);
    __syncthreads();

    // ---- prefetch (depth 2) ----
    const int t0 = blockIdx.x;
    float4 ear = make_float4(0.f, 0.f, 0.f, 0.f);
    int    dsr = 0;
    if (tid < 160)
        reinterpret_cast<float4*>(eab)[tid] =
            reinterpret_cast<const float4*>(edge_attr + (long long)t0 * E_TILE * 5)[tid];
    if (tid < 128)
        dsb[tid] = edge_index[N_EDGES + t0 * E_TILE + tid];
    {
        const int t1 = (t0 + EGRID < N_TILES) ? t0 + EGRID : t0;
        if (tid < 160)
            ear = reinterpret_cast<const float4*>(edge_attr + (long long)t1 * E_TILE * 5)[tid];
        if (tid < 128)
            dsr = edge_index[N_EDGES + t1 * E_TILE + tid];
    }
    __syncthreads();

    const int fRow = (w & 3) * 32 + l;
    const int es0  = (w >> 2) * 64;

    int cur = 0;
    for (int tile = t0; tile < N_TILES; tile += EGRID) {
        const float* eas  = eab + cur * 640;
        const int*   dsti = dsb + cur * 128;

        // ---- layer 1: 5 -> 128, write h1h[k=f][e] (fp16) ----
        {
            float a[20];
            const float4* ap = reinterpret_cast<const float4*>(&eas[(4 * l) * 5]);
#pragma unroll
            for (int q = 0; q < 5; q++) {
                const float4 v = ap[q];
                a[4*q] = v.x; a[4*q+1] = v.y; a[4*q+2] = v.z; a[4*q+3] = v.w;
            }
#pragma unroll
            for (int fi = 0; fi < 16; fi++) {
                const int f = f0 + fi;
                const float bb = b1s[f];
                float v[4];
#pragma unroll
                for (int ei = 0; ei < 4; ei++) {
                    float t = bb;
#pragma unroll
                    for (int j = 0; j < 5; j++)
                        t = fmaf(w1s[f * 5 + j], a[ei * 5 + j], t);
                    v[ei] = leaky(t);
                }
                const __half2 p0 = __floats2half2_rn(v[0], v[1]);
                const __half2 p1 = __floats2half2_rn(v[2], v[3]);
                __half2* dst = reinterpret_cast<__half2*>(&h1h[f * HPH + 4 * l]);
                dst[0] = p0;
                dst[1] = p1;
            }
        }
        __syncthreads();

        // ---- layer 2: acc = W2 @ h1 + b2 (fp32 acc), 4-wide, store fp32 to mf ----
#pragma unroll 1
        for (int n = 0; n < 8; n += 4) {
            wmma::fragment<wmma::accumulator, 16, 16, 16, float> ac[4];
#pragma unroll
            for (int j = 0; j < 4; j++) ac[j] = ab2;
#pragma unroll
            for (int kt = 0; kt < 8; kt++) {
                wmma::fragment<wmma::matrix_b, 16, 16, 16, __half, wmma::row_major> bf[4];
#pragma unroll
                for (int j = 0; j < 4; j++)
                    wmma::load_matrix_sync(bf[j], h1h + kt * 16 * HPH + (n + j) * 16, HPH);
#pragma unroll
                for (int j = 0; j < 4; j++)
                    wmma::mma_sync(ac[j], a2[kt], bf[j], ac[j]);
            }
#pragma unroll
            for (int j = 0; j < 4; j++)
                wmma::store_matrix_sync(mf + f0 * HP + (n + j) * 16, ac[j], HP, wmma::mem_row_major);
        }
        __syncthreads();

        // ---- convert pass: h2h = fp16(leaky(mf)); overlap prefetch shuffle ----
        {
            const int nb = cur ^ 1;
            if (tid < 160) reinterpret_cast<float4*>(eab + nb * 640)[tid] = ear;
            if (tid < 128) dsb[nb * 128 + tid] = dsr;
            const int tn = tile + 2 * EGRID;
            const int tc = (tn < N_TILES) ? tn : t0;
            if (tid < 160)
                ear = reinterpret_cast<const float4*>(edge_attr + (long long)tc * E_TILE * 5)[tid];
            if (tid < 128)
                dsr = edge_index[N_EDGES + tc * E_TILE + tid];
        }
#pragma unroll 4
        for (int i = tid; i < 128 * 32; i += 256) {
            const int f  = i >> 5;
            const int e4 = (i & 31) * 4;
            const float4 v = *reinterpret_cast<const float4*>(&mf[f * HP + e4]);
            __half2* dst = reinterpret_cast<__half2*>(&h2h[f * HPH + e4]);
            dst[0] = __floats2half2_rn(leaky(v.x), leaky(v.y));
            dst[1] = __floats2half2_rn(leaky(v.z), leaky(v.w));
        }
        __syncthreads();

        // ---- layer 3: acc = W3 @ h2 + b3 (fp32 acc), 4-wide, store fp32 to mf ----
#pragma unroll 1
        for (int n = 0; n < 8; n += 4) {
            wmma::fragment<wmma::accumulator, 16, 16, 16, float> ac[4];
#pragma unroll
            for (int j = 0; j < 4; j++) ac[j] = ab3;
#pragma unroll
            for (int kt = 0; kt < 8; kt++) {
                wmma::fragment<wmma::matrix_b, 16, 16, 16, __half, wmma::row_major> bf[4];
#pragma unroll
                for (int j = 0; j < 4; j++)
                    wmma::load_matrix_sync(bf[j], h2h + kt * 16 * HPH + (n + j) * 16, HPH);
#pragma unroll
                for (int j = 0; j < 4; j++)
                    wmma::mma_sync(ac[j], a3[kt], bf[j], ac[j]);
            }
#pragma unroll
            for (int j = 0; j < 4; j++)
                wmma::store_matrix_sync(mf + f0 * HP + (n + j) * 16, ac[j], HP, wmma::mem_row_major);
        }
        __syncthreads();

        // ---- scatter: coalesced red.global.add per edge ----
        {
            const float* mrow = mf + fRow * HP;
#pragma unroll 4
            for (int j = 0; j < 64; j++) {
                const int e = es0 + j;
                const int d = dsti[e];
                red_f32(&g_aggr[(long long)d * D_F + fRow], mrow[e]);
            }
        }
        __syncthreads();
        cur ^= 1;
    }
}

// ---------------- kernel: LayerNorm over concat(x, aggr), tf32 output ----------------
__global__ void k_ln(const float* __restrict__ x,
                     const float* __restrict__ ln_g,
                     const float* __restrict__ ln_b)
{
    const int node = (blockIdx.x * blockDim.x + threadIdx.x) >> 5;
    const int lane = threadIdx.x & 31;
    if (node >= N_NODES) return;

    const float* xr = x      + (long long)node * D_F;
    const float* ar = g_aggr + (long long)node * D_F;
    float v[8];
#pragma unroll
    for (int i = 0; i < 4; i++) v[i]     = xr[lane + 32 * i];
#pragma unroll
    for (int i = 0; i < 4; i++) v[4 + i] = ar[lane + 32 * i];

    float s = 0.f;
#pragma unroll
    for (int i = 0; i < 8; i++) s += v[i];
#pragma unroll
    for (int o = 16; o > 0; o >>= 1) s += __shfl_xor_sync(0xffffffffu, s, o);
    const float mu = s * (1.0f / 256.0f);

    float q = 0.f;
#pragma unroll
    for (int i = 0; i < 8; i++) { const float d = v[i] - mu; q += d * d; }
#pragma unroll
    for (int o = 16; o > 0; o >>= 1) q += __shfl_xor_sync(0xffffffffu, q, o);
    const float rstd = rsqrtf(q * (1.0f / 256.0f) + 1e-5f);

    float* out = g_nrm + (long long)node * D_CAT;
#pragma unroll
    for (int i = 0; i < 8; i++) {
        const int c = (i < 4) ? (lane + 32 * i) : (128 + lane + 32 * (i - 4));
        out[c] = tf32f((v[i] - mu) * rstd * ln_g[c] + ln_b[c]);
    }
}

// ---------------- kernel: wmma tf32 GEMM, cp.async double-buffered (R15) ----------------
// 128m x 64n block tile, 8 warps (4m x 2n), warp tile 32m x 32n (2x2 acc frags).
__global__ void __launch_bounds__(256)
k_wgemm(const float* __restrict__ A, const float* __restrict__ B,
        const float* __restrict__ bias, float* __restrict__ C,
        int M, int N, int K, int doLeaky, int outCvt)
{
    __shared__ float As[2][128 * 36];
    __shared__ float Bs[2][64 * 36];
    __shared__ float bmat[16 * 68];

    const int tid = threadIdx.x;
    const int w  = tid >> 5;
    const int wm = w >> 1;    // 0..3
    const int wn = w & 1;     // 0..1
    int m0 = blockIdx.x * 128; if (m0 > M - 128) m0 = M - 128;
    int n0 = blockIdx.y * 64;  if (n0 > N - 64)  n0 = N - 64;

    for (int i = tid; i < 16 * 64; i += 256) {
        const int r = i >> 6, c = i & 63;
        bmat[r * 68 + c] = bias[n0 + c];
    }
    __syncthreads();

    wmma::fragment<wmma::accumulator, 16, 16, 8, float> acc[2][2];
#pragma unroll
    for (int j = 0; j < 2; j++) {
        wmma::load_matrix_sync(acc[0][j], bmat + wn * 32 + j * 16, 68, wmma::mem_row_major);
        acc[1][j] = acc[0][j];
    }

    const int mm = tid >> 5;
    const int kk = tid & 31;
    const int nChunks = (K + 31) / 32;

    auto stage = [&](int c, int b) {
        const int ka = c * 32 + kk;
        const bool kok = (ka < K);
#pragma unroll
        for (int r = 0; r < 16; r++) {
            const int row = mm + r * 8;
            float* dA = &As[b][row * 36 + kk];
            if (kok) cp_async4((unsigned)__cvta_generic_to_shared(dA),
                               A + (long long)(m0 + row) * K + ka);
            else     *dA = 0.f;
        }
#pragma unroll
        for (int r = 0; r < 8; r++) {
            const int row = mm + r * 8;
            float* dB = &Bs[b][row * 36 + kk];
            if (kok) cp_async4((unsigned)__cvta_generic_to_shared(dB),
                               B + (long long)(n0 + row) * K + ka);
            else     *dB = 0.f;
        }
    };

    stage(0, 0);
    CP_COMMIT();

    for (int c = 0; c < nChunks; c++) {
        const int buf = c & 1;
        if (c + 1 < nChunks) {
            stage(c + 1, buf ^ 1);
            CP_COMMIT();
            CP_WAIT(1);
        } else {
            CP_WAIT(0);
        }
        __syncthreads();
#pragma unroll
        for (int kt = 0; kt < 4; kt++) {
            wmma::fragment<wmma::matrix_a, 16, 16, 8, wmma::precision::tf32, wmma::row_major> af[2];
            wmma::fragment<wmma::matrix_b, 16, 16, 8, wmma::precision::tf32, wmma::col_major> bf[2];
#pragma unroll
            for (int i = 0; i < 2; i++)
                wmma::load_matrix_sync(af[i], &As[buf][(wm * 32 + i * 16) * 36 + kt * 8], 36);
#pragma unroll
            for (int j = 0; j < 2; j++)
                wmma::load_matrix_sync(bf[j], &Bs[buf][(wn * 32 + j * 16) * 36 + kt * 8], 36);
#pragma unroll
            for (int i = 0; i < 2; i++)
#pragma unroll
                for (int j = 0; j < 2; j++)
                    wmma::mma_sync(acc[i][j], af[i], bf[j], acc[i][j]);
        }
        __syncthreads();
    }

#pragma unroll
    for (int i = 0; i < 2; i++)
#pragma unroll
        for (int j = 0; j < 2; j++) {
#pragma unroll
            for (int e = 0; e < acc[i][j].num_elements; e++) {
                float v = acc[i][j].x[e];
                if (doLeaky) v = leaky(v);
                if (outCvt)  v = tf32f(v);
                acc[i][j].x[e] = v;
            }
            wmma::store_matrix_sync(
                C + (long long)(m0 + wm * 32 + i * 16) * N + n0 + wn * 32 + j * 16,
                acc[i][j], N, wmma::mem_row_major);
        }
}

// ---------------- launch ----------------
extern "C" void kernel_launch(void* const* d_in, const int* in_sizes, int n_in,
                              void* d_out, int out_size)
{
    const float* x          = (const float*)d_in[0];
    const int*   edge_index = (const int*)d_in[1];
    const float* edge_attr  = (const float*)d_in[2];
    const float* Wm1 = (const float*)d_in[3];
    const float* bm1 = (const float*)d_in[4];
    const float* Wm2 = (const float*)d_in[5];
    const float* bm2 = (const float*)d_in[6];
    const float* Wm3 = (const float*)d_in[7];
    const float* bm3 = (const float*)d_in[8];
    const float* ln_g = (const float*)d_in[9];
    const float* ln_b = (const float*)d_in[10];
    const float* Wu1 = (const float*)d_in[11];
    const float* bu1 = (const float*)d_in[12];
    const float* Wu2 = (const float*)d_in[13];
    const float* bu2 = (const float*)d_in[14];
    const float* Wu3 = (const float*)d_in[15];
    const float* bu3 = (const float*)d_in[16];
    float* out = (float*)d_out;

    void *p_nrm = nullptr, *p_u1 = nullptr, *p_u2 = nullptr;
    void *p_w1 = nullptr, *p_w2 = nullptr, *p_w3 = nullptr;
    cudaGetSymbolAddress(&p_nrm, g_nrm);
    cudaGetSymbolAddress(&p_u1,  g_u1);
    cudaGetSymbolAddress(&p_u2,  g_u2);
    cudaGetSymbolAddress(&p_w1,  g_w1t);
    cudaGetSymbolAddress(&p_w2,  g_w2t);
    cudaGetSymbolAddress(&p_w3,  g_w3t);

    cudaFuncSetAttribute(k_edge, cudaFuncAttributeMaxDynamicSharedMemorySize, EDGE_SMEM_BYTES);

    k_zero<<<2048, 256>>>();
    k_prep<<<64, 256>>>(Wu1, Wu2, Wu3);
    k_nop<<<1, 32>>>();

    k_edge<<<EGRID, 256, EDGE_SMEM_BYTES>>>(edge_attr, edge_index,
                                            Wm1, bm1, Wm2, bm2, Wm3, bm3);

    k_ln<<<(N_NODES * 32 + 255) / 256, 256>>>(x, ln_g, ln_b);

    dim3 g1((N_NODES + 127) / 128, (D_U1 + 63) / 64);
    k_wgemm<<<g1, 256>>>((const float*)p_nrm, (const float*)p_w1, bu1, (float*)p_u1,
                         N_NODES, D_U1, D_CAT, 1, 1);

    dim3 g2((N_NODES + 127) / 128, (D_U2 + 63) / 64);
    k_wgemm<<<g2, 256>>>((const float*)p_u1, (const float*)p_w2, bu2, (float*)p_u2,
                         N_NODES, D_U2, D_U1, 1, 1);

    dim3 g3((N_NODES + 127) / 128, (D_OUT + 63) / 64);
    k_wgemm<<<g3, 256>>>((const float*)p_u2, (const float*)p_w3, bu3, out,
                         N_NODES, D_OUT, D_U2, 0, 0);
}